// round 1
// baseline (speedup 1.0000x reference)
#include <cuda_runtime.h>
#include <cuda_bf16.h>
#include <cstdint>

// Problem constants
#define NN   4096      // nodes
#define PP   32768     // pairs
#define EE   4096      // events
#define DD   128       // embed dim
#define RR   4
#define KK   16
#define NW   128       // 4096 bits / 32 = words per adjacency row

// ---------------- device scratch (no allocations allowed) ----------------
__device__ unsigned g_bits[NN * NW];     // 2 MB bitpacked adjacency
__device__ float    g_deg [NN];
__device__ float    g_C   [NN];
__device__ float    g_proj[NN * DD];     // 2 MB
__device__ float    g_eps [NN * DD];     // 2 MB
__device__ float    g_alpha;

// ---------------- K1: bitpack adjacency rows + degree ----------------
__global__ void k_pack(const int* __restrict__ adj) {
    int row  = blockIdx.x;
    int t    = threadIdx.x;          // 128 threads
    int lane = t & 31, warp = t >> 5;
    const int* a = adj + (size_t)row * NN;
    int deg = 0;
    #pragma unroll 4
    for (int i = 0; i < 32; i++) {
        int v = a[i * 128 + t];
        unsigned m = __ballot_sync(0xffffffffu, v != 0);
        if (lane == 0) {
            g_bits[row * NW + i * 4 + warp] = m;
            deg += __popc(m);
        }
    }
    __shared__ int sdeg[4];
    if (lane == 0) sdeg[warp] = deg;
    __syncthreads();
    if (t == 0) g_deg[row] = (float)(sdeg[0] + sdeg[1] + sdeg[2] + sdeg[3]);
}

// ---------------- K2: triangles via AND+popcount, clustering coeff C ----------------
__global__ void k_tri() {
    int i = blockIdx.x;
    int t = threadIdx.x;             // 128 threads
    __shared__ __align__(16) unsigned sri[NW];
    sri[t] = g_bits[i * NW + t];
    __syncthreads();
    unsigned w = sri[t];
    int cnt = 0;
    const uint4* ri = (const uint4*)sri;
    while (w) {
        int b = __ffs(w) - 1;
        w &= w - 1;
        int j = t * 32 + b;          // neighbor index
        const uint4* rj = (const uint4*)&g_bits[j * NW];
        int s = 0;
        #pragma unroll 8
        for (int v = 0; v < 32; v++) {
            uint4 x = rj[v];
            uint4 y = ri[v];
            s += __popc(x.x & y.x) + __popc(x.y & y.y)
               + __popc(x.z & y.z) + __popc(x.w & y.w);
        }
        cnt += s;
    }
    #pragma unroll
    for (int o = 16; o; o >>= 1) cnt += __shfl_down_sync(0xffffffffu, cnt, o);
    __shared__ int sc[4];
    if ((t & 31) == 0) sc[t >> 5] = cnt;
    __syncthreads();
    if (t == 0) {
        float tri = (float)(sc[0] + sc[1] + sc[2] + sc[3]);
        float d   = g_deg[i];
        float den = d * (d - 1.0f);
        if (den == 0.0f) den = 1e-6f;
        g_C[i] = 2.0f * tri / den;
    }
}

// ---------------- K3: type-selected projection  proj[n] = emb[n] @ W_proj[type[n]] ----------------
// TN=8 nodes per block, 128 threads (thread = output dim e)
__global__ void k_proj(const float* __restrict__ emb,
                       const float* __restrict__ Wp,
                       const int*   __restrict__ ntype) {
    int e  = threadIdx.x;
    int n0 = blockIdx.x * 8;
    __shared__ float semb[8][DD];
    __shared__ int   sty[8];
    #pragma unroll
    for (int n = 0; n < 8; n++) semb[n][e] = emb[(n0 + n) * DD + e];
    if (e < 8) sty[e] = ntype[n0 + e];
    __syncthreads();
    int ty[8];
    #pragma unroll
    for (int n = 0; n < 8; n++) ty[n] = sty[n];
    float acc[8] = {0.f,0.f,0.f,0.f,0.f,0.f,0.f,0.f};
    #pragma unroll 4
    for (int d = 0; d < DD; d++) {
        float w0 = Wp[(0 * DD + d) * DD + e];
        float w1 = Wp[(1 * DD + d) * DD + e];
        float w2 = Wp[(2 * DD + d) * DD + e];
        #pragma unroll
        for (int n = 0; n < 8; n++) {
            float wv = (ty[n] == 0) ? w0 : ((ty[n] == 1) ? w1 : w2);
            acc[n] += semb[n][d] * wv;
        }
    }
    #pragma unroll
    for (int n = 0; n < 8; n++) g_proj[(n0 + n) * DD + e] = acc[n];
}

// ---------------- K4: neighbor aggregation + eps = sigmoid(mean_r(h_r @ W_r + b_r)) ----------------
// TN=8 nodes per block, 128 threads (thread = output dim e)
__global__ void k_eps(const float* __restrict__ emb,
                      const int*   __restrict__ nidx,
                      const float* __restrict__ Wb,
                      const float* __restrict__ bb) {
    int e  = threadIdx.x;
    int n0 = blockIdx.x * 8;
    __shared__ float sx[8][RR * DD];     // 16 KB: h_r tiles (rd-major)
    __shared__ int   sid[8 * RR * KK];   // 64 ids per node
    for (int q = e; q < 8 * 64; q += 128) sid[q] = nidx[n0 * 64 + q];
    __syncthreads();
    #pragma unroll
    for (int n = 0; n < 8; n++) {
        #pragma unroll
        for (int r = 0; r < RR; r++) {
            float s = 0.f;
            #pragma unroll
            for (int k = 0; k < KK; k++) {
                int nid = sid[n * 64 + r * KK + k];
                s += emb[nid * DD + e];
            }
            sx[n][r * DD + e] = s * (1.0f / 16.0f);
        }
    }
    __syncthreads();
    float acc[8] = {0.f,0.f,0.f,0.f,0.f,0.f,0.f,0.f};
    #pragma unroll 4
    for (int rd = 0; rd < RR * DD; rd++) {
        float wv = Wb[rd * DD + e];      // W_beta flattened (r*D+d, e)
        #pragma unroll
        for (int n = 0; n < 8; n++) acc[n] += sx[n][rd] * wv;
    }
    float bsum = bb[e] + bb[DD + e] + bb[2 * DD + e] + bb[3 * DD + e];
    #pragma unroll
    for (int n = 0; n < 8; n++) {
        float h = (acc[n] + bsum) * 0.25f;
        g_eps[(n0 + n) * DD + e] = 1.0f / (1.0f + expf(-h));
    }
}

// ---------------- K5: sum_alpha reduction ----------------
__global__ void k_alpha(const float* __restrict__ tev,
                        const float* __restrict__ theta_p) {
    float th = theta_p[0];
    float s  = 0.f;
    for (int i = threadIdx.x; i < EE; i += 256)
        s += expf(-th * (1.0f - tev[i]));
    #pragma unroll
    for (int o = 16; o; o >>= 1) s += __shfl_down_sync(0xffffffffu, s, o);
    __shared__ float sw[8];
    int lane = threadIdx.x & 31, warp = threadIdx.x >> 5;
    if (lane == 0) sw[warp] = s;
    __syncthreads();
    if (threadIdx.x == 0) {
        float tot = 0.f;
        #pragma unroll
        for (int i = 0; i < 8; i++) tot += sw[i];
        g_alpha = tot;
    }
}

// ---------------- K6: per-pair score (warp per pair) ----------------
__global__ void k_pairs(const int*   __restrict__ pairs,
                        const float* __restrict__ emb,
                        const float* __restrict__ q1p,
                        const float* __restrict__ q2p,
                        float*       __restrict__ out) {
    int gw   = (blockIdx.x * blockDim.x + threadIdx.x) >> 5;
    int lane = threadIdx.x & 31;
    if (gw >= PP) return;
    int pm = pairs[gw * 2 + 0];
    int pn = pairs[gw * 2 + 1];

    float4 a  = ((const float4*)&g_proj[pm * DD])[lane];
    float4 b  = ((const float4*)&g_proj[pn * DD])[lane];
    float dx0 = a.x - b.x, dx1 = a.y - b.y, dx2 = a.z - b.z, dx3 = a.w - b.w;
    float s1  = dx0*dx0 + dx1*dx1 + dx2*dx2 + dx3*dx3;

    float4 ea = ((const float4*)&emb[pm * DD])[lane];
    float4 eb = ((const float4*)&emb[pn * DD])[lane];
    float e0 = ea.x - eb.x, e1 = ea.y - eb.y, e2 = ea.z - eb.z, e3 = ea.w - eb.w;
    float s2 = e0*e0 + e1*e1 + e2*e2 + e3*e3;

    float4 pa = ((const float4*)&g_eps[pm * DD])[lane];
    float4 pb = ((const float4*)&g_eps[pn * DD])[lane];
    float s3  = pa.x*pb.x + pa.y*pb.y + pa.z*pb.z + pa.w*pb.w;

    uint4 bm = ((const uint4*)&g_bits[pm * NW])[lane];
    uint4 bn = ((const uint4*)&g_bits[pn * NW])[lane];
    float cs = 0.f;
    {
        unsigned ws[4] = { bm.x & bn.x, bm.y & bn.y, bm.z & bn.z, bm.w & bn.w };
        #pragma unroll
        for (int c = 0; c < 4; c++) {
            unsigned w = ws[c];
            int j0 = (lane * 4 + c) * 32;
            while (w) {
                int bpos = __ffs(w) - 1;
                w &= w - 1;
                cs += g_C[j0 + bpos];
            }
        }
    }

    #pragma unroll
    for (int o = 16; o; o >>= 1) {
        s1 += __shfl_xor_sync(0xffffffffu, s1, o);
        s2 += __shfl_xor_sync(0xffffffffu, s2, o);
        s3 += __shfl_xor_sync(0xffffffffu, s3, o);
        cs += __shfl_xor_sync(0xffffffffu, cs, o);
    }

    if (lane == 0) {
        float gamma = -sqrtf(s1);
        float g     = -s2;
        float lamb  = gamma + g_alpha + cs * g + s3 * (1.0f / (float)DD);
        float lam   = expf(lamb);
        float z     = q1p[0] * lam + q2p[0];
        out[gw] = 1.0f / (1.0f + expf(-z));
    }
}

// ---------------- launcher ----------------
extern "C" void kernel_launch(void* const* d_in, const int* in_sizes, int n_in,
                              void* d_out, int out_size) {
    const int*   pairs   = (const int*)  d_in[0];
    const int*   adj     = (const int*)  d_in[1];
    const int*   nidx    = (const int*)  d_in[2];
    const int*   ntype   = (const int*)  d_in[3];
    const float* tev     = (const float*)d_in[4];
    const float* emb     = (const float*)d_in[5];
    const float* Wp      = (const float*)d_in[6];
    const float* Wb      = (const float*)d_in[7];
    const float* bb      = (const float*)d_in[8];
    const float* theta_p = (const float*)d_in[9];
    const float* q1p     = (const float*)d_in[10];
    const float* q2p     = (const float*)d_in[11];
    float*       out     = (float*)d_out;

    k_pack <<<NN, 128>>>(adj);
    k_tri  <<<NN, 128>>>();
    k_proj <<<NN / 8, 128>>>(emb, Wp, ntype);
    k_eps  <<<NN / 8, 128>>>(emb, nidx, Wb, bb);
    k_alpha<<<1, 256>>>(tev, theta_p);
    k_pairs<<<PP / 8, 256>>>(pairs, emb, q1p, q2p, out);
}

// round 2
// speedup vs baseline: 1.0619x; 1.0619x over previous
#include <cuda_runtime.h>
#include <cuda_bf16.h>
#include <cstdint>

// Problem constants
#define NN   4096      // nodes
#define PP   32768     // pairs
#define EE   4096      // events
#define DD   128       // embed dim
#define RR   4
#define KK   16
#define NW   128       // 4096 bits / 32 = words per adjacency row
#define TNE  16        // node tile for GEMM kernels

// ---------------- device scratch (no allocations allowed) ----------------
__device__ unsigned g_bits[NN * NW];     // 2 MB bitpacked adjacency
__device__ float    g_deg [NN];
__device__ float    g_C   [NN];
__device__ float    g_proj[NN * DD];     // 2 MB
__device__ float    g_eps [NN * DD];     // 2 MB
__device__ float    g_hbar[NN * RR * DD];// 8 MB  h_bar[n][r*128+d]
__device__ float    g_alpha;

// ---------------- packed fp32x2 helpers (sm_100+) ----------------
__device__ __forceinline__ unsigned long long pk(float x, float y) {
    unsigned long long r;
    asm("mov.b64 %0, {%1, %2};" : "=l"(r) : "f"(x), "f"(y));
    return r;
}
__device__ __forceinline__ void upk(float& x, float& y, unsigned long long v) {
    asm("mov.b64 {%0, %1}, %2;" : "=f"(x), "=f"(y) : "l"(v));
}
__device__ __forceinline__ void ffma2(unsigned long long& d,
                                      unsigned long long a,
                                      unsigned long long b) {
    asm("fma.rn.f32x2 %0, %1, %2, %0;" : "+l"(d) : "l"(a), "l"(b));
}

// ---------------- K1: bitpack adjacency rows + degree ----------------
__global__ void k_pack(const int* __restrict__ adj) {
    int row  = blockIdx.x;
    int t    = threadIdx.x;          // 128 threads
    int lane = t & 31, warp = t >> 5;
    const int* a = adj + (size_t)row * NN;
    int deg = 0;
    #pragma unroll 4
    for (int i = 0; i < 32; i++) {
        int v = a[i * 128 + t];
        unsigned m = __ballot_sync(0xffffffffu, v != 0);
        if (lane == 0) {
            g_bits[row * NW + i * 4 + warp] = m;
            deg += __popc(m);
        }
    }
    __shared__ int sdeg[4];
    if (lane == 0) sdeg[warp] = deg;
    __syncthreads();
    if (t == 0) g_deg[row] = (float)(sdeg[0] + sdeg[1] + sdeg[2] + sdeg[3]);
}

// ---------------- K2: triangles via AND+popcount, clustering coeff C ----------------
__global__ void k_tri() {
    int i = blockIdx.x;
    int t = threadIdx.x;             // 128 threads
    __shared__ __align__(16) unsigned sri[NW];
    sri[t] = g_bits[i * NW + t];
    __syncthreads();
    unsigned w = sri[t];
    int cnt = 0;
    const uint4* ri = (const uint4*)sri;
    while (w) {
        int b = __ffs(w) - 1;
        w &= w - 1;
        int j = t * 32 + b;          // neighbor index
        const uint4* rj = (const uint4*)&g_bits[j * NW];
        int s = 0;
        #pragma unroll 8
        for (int v = 0; v < 32; v++) {
            uint4 x = rj[v];
            uint4 y = ri[v];
            s += __popc(x.x & y.x) + __popc(x.y & y.y)
               + __popc(x.z & y.z) + __popc(x.w & y.w);
        }
        cnt += s;
    }
    #pragma unroll
    for (int o = 16; o; o >>= 1) cnt += __shfl_down_sync(0xffffffffu, cnt, o);
    __shared__ int sc[4];
    if ((t & 31) == 0) sc[t >> 5] = cnt;
    __syncthreads();
    if (t == 0) {
        float tri = (float)(sc[0] + sc[1] + sc[2] + sc[3]);
        float d   = g_deg[i];
        float den = d * (d - 1.0f);
        if (den == 0.0f) den = 1e-6f;
        g_C[i] = 2.0f * tri / den;
    }
}

// ---------------- K3: type-selected projection ----------------
// 16-node tile, 512 threads: group g (of 4) handles d in [g*32, g*32+32)
__global__ void k_proj(const float* __restrict__ emb,
                       const float* __restrict__ Wp,
                       const int*   __restrict__ ntype) {
    __shared__ __align__(16) float semb[DD * 20];   // semb_t[d][n], pad 20
    __shared__ float sred[3 * TNE * DD];            // 24 KB partials
    __shared__ int   sty[TNE];
    int tid = threadIdx.x;
    int e = tid & 127, g = tid >> 7;
    int n0 = blockIdx.x * TNE;

    for (int idx = tid; idx < TNE * DD; idx += 512) {
        int d = idx & 127, n = idx >> 7;
        semb[d * 20 + n] = emb[(n0 + n) * DD + d];
    }
    if (tid < TNE) sty[tid] = ntype[n0 + tid];
    __syncthreads();

    int ty[TNE];
    #pragma unroll
    for (int n = 0; n < TNE; n++) ty[n] = sty[n];

    float acc[TNE];
    #pragma unroll
    for (int n = 0; n < TNE; n++) acc[n] = 0.f;

    int dbase = g * 32;
    #pragma unroll 2
    for (int i = 0; i < 32; i++) {
        int d = dbase + i;
        float w0 = Wp[(0 * DD + d) * DD + e];
        float w1 = Wp[(1 * DD + d) * DD + e];
        float w2 = Wp[(2 * DD + d) * DD + e];
        const float4* row = (const float4*)&semb[d * 20];
        #pragma unroll
        for (int q = 0; q < 4; q++) {
            float4 v = row[q];
            {
                int n = 4*q+0; float wv = (ty[n]==0)?w0:((ty[n]==1)?w1:w2); acc[n] += v.x * wv;
            }{
                int n = 4*q+1; float wv = (ty[n]==0)?w0:((ty[n]==1)?w1:w2); acc[n] += v.y * wv;
            }{
                int n = 4*q+2; float wv = (ty[n]==0)?w0:((ty[n]==1)?w1:w2); acc[n] += v.z * wv;
            }{
                int n = 4*q+3; float wv = (ty[n]==0)?w0:((ty[n]==1)?w1:w2); acc[n] += v.w * wv;
            }
        }
    }
    if (g > 0) {
        #pragma unroll
        for (int n = 0; n < TNE; n++)
            sred[((g - 1) * TNE + n) * DD + e] = acc[n];
    }
    __syncthreads();
    if (g == 0) {
        #pragma unroll
        for (int n = 0; n < TNE; n++) {
            float t = acc[n] + sred[n * DD + e]
                             + sred[(TNE + n) * DD + e]
                             + sred[(2 * TNE + n) * DD + e];
            g_proj[(n0 + n) * DD + e] = t;
        }
    }
}

// ---------------- K4a: neighbor gather -> h_bar ----------------
// one block per (node, r): 16384 blocks, 128 threads (thread = dim e)
__global__ void k_gather(const float* __restrict__ emb,
                         const int*   __restrict__ nidx) {
    int b = blockIdx.x;              // n*RR + r
    int e = threadIdx.x;
    __shared__ int sid[KK];
    if (e < KK) sid[e] = nidx[b * KK + e];
    __syncthreads();
    float s = 0.f;
    #pragma unroll
    for (int k = 0; k < KK; k++)
        s += __ldg(&emb[sid[k] * DD + e]);
    g_hbar[b * DD + e] = s * (1.0f / (float)KK);
}

// ---------------- K4b: eps GEMM  eps = sigmoid((h_bar @ Wb + sum_r b)/4) ----------------
// 16-node tile, 512 threads: group g (of 4) handles rd in [g*128, g*128+128)
// packed f32x2 FMA: acc[q] holds nodes (2q, 2q+1)
__global__ void k_egemm(const float* __restrict__ Wb,
                        const float* __restrict__ bb) {
    __shared__ __align__(16) float sbuf[512 * 20];  // 40 KB: s_h[rd][n] pad 20; reused for reduce
    int tid = threadIdx.x;
    int e = tid & 127, g = tid >> 7;
    int n0 = blockIdx.x * TNE;

    for (int idx = tid; idx < TNE * 512; idx += 512) {
        int rd = idx & 511, n = idx >> 9;
        sbuf[rd * 20 + n] = g_hbar[(n0 + n) * 512 + rd];
    }
    __syncthreads();

    unsigned long long acc[8];
    #pragma unroll
    for (int q = 0; q < 8; q++) acc[q] = 0ull;

    int rdbase = g * 128;
    #pragma unroll 2
    for (int i = 0; i < 128; i++) {
        int rd = rdbase + i;
        float w = Wb[rd * DD + e];
        unsigned long long w2 = pk(w, w);
        const ulonglong2* row = (const ulonglong2*)&sbuf[rd * 20];
        #pragma unroll
        for (int q = 0; q < 4; q++) {
            ulonglong2 v = row[q];
            ffma2(acc[2 * q],     v.x, w2);
            ffma2(acc[2 * q + 1], v.y, w2);
        }
    }
    float a[TNE];
    #pragma unroll
    for (int q = 0; q < 8; q++) upk(a[2 * q], a[2 * q + 1], acc[q]);

    __syncthreads();                 // everyone done reading sbuf
    if (g > 0) {
        #pragma unroll
        for (int n = 0; n < TNE; n++)
            sbuf[((g - 1) * TNE + n) * DD + e] = a[n];
    }
    __syncthreads();
    if (g == 0) {
        float bsum = bb[e] + bb[DD + e] + bb[2 * DD + e] + bb[3 * DD + e];
        #pragma unroll
        for (int n = 0; n < TNE; n++) {
            float t = a[n] + sbuf[n * DD + e]
                           + sbuf[(TNE + n) * DD + e]
                           + sbuf[(2 * TNE + n) * DD + e];
            float h = (t + bsum) * 0.25f;
            g_eps[(n0 + n) * DD + e] = 1.0f / (1.0f + expf(-h));
        }
    }
}

// ---------------- K5: sum_alpha reduction ----------------
__global__ void k_alpha(const float* __restrict__ tev,
                        const float* __restrict__ theta_p) {
    float th = theta_p[0];
    float s  = 0.f;
    for (int i = threadIdx.x; i < EE; i += 256)
        s += expf(-th * (1.0f - tev[i]));
    #pragma unroll
    for (int o = 16; o; o >>= 1) s += __shfl_down_sync(0xffffffffu, s, o);
    __shared__ float sw[8];
    int lane = threadIdx.x & 31, warp = threadIdx.x >> 5;
    if (lane == 0) sw[warp] = s;
    __syncthreads();
    if (threadIdx.x == 0) {
        float tot = 0.f;
        #pragma unroll
        for (int i = 0; i < 8; i++) tot += sw[i];
        g_alpha = tot;
    }
}

// ---------------- K6: per-pair score (warp per pair) ----------------
__global__ void k_pairs(const int*   __restrict__ pairs,
                        const float* __restrict__ emb,
                        const float* __restrict__ q1p,
                        const float* __restrict__ q2p,
                        float*       __restrict__ out) {
    int gw   = (blockIdx.x * blockDim.x + threadIdx.x) >> 5;
    int lane = threadIdx.x & 31;
    if (gw >= PP) return;
    int pm = pairs[gw * 2 + 0];
    int pn = pairs[gw * 2 + 1];

    float4 a  = ((const float4*)&g_proj[pm * DD])[lane];
    float4 b  = ((const float4*)&g_proj[pn * DD])[lane];
    float dx0 = a.x - b.x, dx1 = a.y - b.y, dx2 = a.z - b.z, dx3 = a.w - b.w;
    float s1  = dx0*dx0 + dx1*dx1 + dx2*dx2 + dx3*dx3;

    float4 ea = ((const float4*)&emb[pm * DD])[lane];
    float4 eb = ((const float4*)&emb[pn * DD])[lane];
    float e0 = ea.x - eb.x, e1 = ea.y - eb.y, e2 = ea.z - eb.z, e3 = ea.w - eb.w;
    float s2 = e0*e0 + e1*e1 + e2*e2 + e3*e3;

    float4 pa = ((const float4*)&g_eps[pm * DD])[lane];
    float4 pb = ((const float4*)&g_eps[pn * DD])[lane];
    float s3  = pa.x*pb.x + pa.y*pb.y + pa.z*pb.z + pa.w*pb.w;

    uint4 bm = ((const uint4*)&g_bits[pm * NW])[lane];
    uint4 bn = ((const uint4*)&g_bits[pn * NW])[lane];
    float cs = 0.f;
    {
        unsigned ws[4] = { bm.x & bn.x, bm.y & bn.y, bm.z & bn.z, bm.w & bn.w };
        #pragma unroll
        for (int c = 0; c < 4; c++) {
            unsigned w = ws[c];
            int j0 = (lane * 4 + c) * 32;
            while (w) {
                int bpos = __ffs(w) - 1;
                w &= w - 1;
                cs += g_C[j0 + bpos];
            }
        }
    }

    #pragma unroll
    for (int o = 16; o; o >>= 1) {
        s1 += __shfl_xor_sync(0xffffffffu, s1, o);
        s2 += __shfl_xor_sync(0xffffffffu, s2, o);
        s3 += __shfl_xor_sync(0xffffffffu, s3, o);
        cs += __shfl_xor_sync(0xffffffffu, cs, o);
    }

    if (lane == 0) {
        float gamma = -sqrtf(s1);
        float g     = -s2;
        float lamb  = gamma + g_alpha + cs * g + s3 * (1.0f / (float)DD);
        float lam   = expf(lamb);
        float z     = q1p[0] * lam + q2p[0];
        out[gw] = 1.0f / (1.0f + expf(-z));
    }
}

// ---------------- launcher ----------------
extern "C" void kernel_launch(void* const* d_in, const int* in_sizes, int n_in,
                              void* d_out, int out_size) {
    const int*   pairs   = (const int*)  d_in[0];
    const int*   adj     = (const int*)  d_in[1];
    const int*   nidx    = (const int*)  d_in[2];
    const int*   ntype   = (const int*)  d_in[3];
    const float* tev     = (const float*)d_in[4];
    const float* emb     = (const float*)d_in[5];
    const float* Wp      = (const float*)d_in[6];
    const float* Wb      = (const float*)d_in[7];
    const float* bb      = (const float*)d_in[8];
    const float* theta_p = (const float*)d_in[9];
    const float* q1p     = (const float*)d_in[10];
    const float* q2p     = (const float*)d_in[11];
    float*       out     = (float*)d_out;

    k_pack  <<<NN, 128>>>(adj);
    k_tri   <<<NN, 128>>>();
    k_proj  <<<NN / TNE, 512>>>(emb, Wp, ntype);
    k_gather<<<NN * RR, 128>>>(emb, nidx);
    k_egemm <<<NN / TNE, 512>>>(Wb, bb);
    k_alpha <<<1, 256>>>(tev, theta_p);
    k_pairs <<<PP / 8, 256>>>(pairs, emb, q1p, q2p, out);
}

// round 3
// speedup vs baseline: 1.1110x; 1.0462x over previous
#include <cuda_runtime.h>
#include <cuda_bf16.h>
#include <cstdint>

// Problem constants
#define NN   4096
#define PP   32768
#define EE   4096
#define DD   128
#define RR   4
#define KK   16
#define NW   128       // 4096 bits / 32 words per adjacency row

// role block ranges in K_A
#define PACK_B 4096
#define PROJ_B 512      // 8 nodes per block
#define GATH_B 8192     // 2 (node,r) units per block
#define ALPHA_B0 (PACK_B + PROJ_B + GATH_B)   // 12800
#define GRID_A   (ALPHA_B0 + 1)

// role block ranges in K_B
#define TRI_B  1024     // 4 rows per block
#define EG_B   256      // 16 nodes per block

// ---------------- device scratch ----------------
__device__ unsigned g_bits[NN * NW];
__device__ float    g_deg [NN];
__device__ float    g_C   [NN];
__device__ float    g_proj[NN * DD];
__device__ float    g_eps [NN * DD];
__device__ float    g_hbar[NN * RR * DD];   // [n][r*128+d]
__device__ float    g_alpha;

// ---------------- packed fp32x2 helpers (sm_100+) ----------------
__device__ __forceinline__ unsigned long long pk(float x, float y) {
    unsigned long long r;
    asm("mov.b64 %0, {%1, %2};" : "=l"(r) : "f"(x), "f"(y));
    return r;
}
__device__ __forceinline__ void upk(float& x, float& y, unsigned long long v) {
    asm("mov.b64 {%0, %1}, %2;" : "=f"(x), "=f"(y) : "l"(v));
}
__device__ __forceinline__ void ffma2(unsigned long long& d,
                                      unsigned long long a,
                                      unsigned long long b) {
    asm("fma.rn.f32x2 %0, %1, %2, %0;" : "+l"(d) : "l"(a), "l"(b));
}

// =======================================================================
// K_A: pack | proj | gather | alpha  (256 threads, role by blockIdx)
// =======================================================================
__global__ void k_A(const int*   __restrict__ adj,
                    const float* __restrict__ emb,
                    const float* __restrict__ Wp,
                    const int*   __restrict__ ntype,
                    const int*   __restrict__ nidx,
                    const float* __restrict__ tev,
                    const float* __restrict__ theta_p) {
    __shared__ __align__(16) float semb[DD * 12];   // proj: [d][n], pad 12
    __shared__ float sred[8 * DD];                  // proj partials
    __shared__ int   sty[8];
    __shared__ int   sdeg[8];                       // pack
    __shared__ int   sid[2][KK];                    // gather
    __shared__ float sw[8];                         // alpha

    int b   = blockIdx.x;
    int tid = threadIdx.x;

    if (b < PACK_B) {
        // ---- bitpack adjacency row + degree ----
        int row  = b;
        int lane = tid & 31, w = tid >> 5;          // 8 warps
        const int* a = adj + (size_t)row * NN;
        int deg = 0;
        #pragma unroll 4
        for (int i = 0; i < 16; i++) {
            int word = i * 8 + w;                   // 0..127
            int v = a[word * 32 + lane];
            unsigned m = __ballot_sync(0xffffffffu, v != 0);
            if (lane == 0) {
                g_bits[row * NW + word] = m;
                deg += __popc(m);
            }
        }
        if (lane == 0) sdeg[w] = deg;
        __syncthreads();
        if (tid == 0) {
            int s = 0;
            #pragma unroll
            for (int i = 0; i < 8; i++) s += sdeg[i];
            g_deg[row] = (float)s;
        }
    } else if (b < PACK_B + PROJ_B) {
        // ---- type-selected projection, 8-node tile ----
        int n0 = (b - PACK_B) * 8;
        int e  = tid & 127, g = tid >> 7;           // g in {0,1}
        for (int idx = tid; idx < 8 * DD; idx += 256) {
            int d = idx & 127, n = idx >> 7;
            semb[d * 12 + n] = emb[(n0 + n) * DD + d];
        }
        if (tid < 8) sty[tid] = ntype[n0 + tid];
        __syncthreads();
        int ty[8];
        #pragma unroll
        for (int n = 0; n < 8; n++) ty[n] = sty[n];
        float acc[8] = {0.f,0.f,0.f,0.f,0.f,0.f,0.f,0.f};
        int dbase = g * 64;
        #pragma unroll 4
        for (int i = 0; i < 64; i++) {
            int d = dbase + i;
            float w0 = Wp[(0 * DD + d) * DD + e];
            float w1 = Wp[(1 * DD + d) * DD + e];
            float w2 = Wp[(2 * DD + d) * DD + e];
            const float4* row4 = (const float4*)&semb[d * 12];
            #pragma unroll
            for (int q = 0; q < 2; q++) {
                float4 v = row4[q];
                { int n=4*q+0; float wv=(ty[n]==0)?w0:((ty[n]==1)?w1:w2); acc[n]+=v.x*wv; }
                { int n=4*q+1; float wv=(ty[n]==0)?w0:((ty[n]==1)?w1:w2); acc[n]+=v.y*wv; }
                { int n=4*q+2; float wv=(ty[n]==0)?w0:((ty[n]==1)?w1:w2); acc[n]+=v.z*wv; }
                { int n=4*q+3; float wv=(ty[n]==0)?w0:((ty[n]==1)?w1:w2); acc[n]+=v.w*wv; }
            }
        }
        if (g == 1) {
            #pragma unroll
            for (int n = 0; n < 8; n++) sred[n * DD + e] = acc[n];
        }
        __syncthreads();
        if (g == 0) {
            #pragma unroll
            for (int n = 0; n < 8; n++)
                g_proj[(n0 + n) * DD + e] = acc[n] + sred[n * DD + e];
        }
    } else if (b < ALPHA_B0) {
        // ---- neighbor gather -> h_bar, 2 units per block ----
        int gb   = b - (PACK_B + PROJ_B);
        int sub  = tid >> 7;
        int unit = gb * 2 + sub;                    // n*RR + r
        int e    = tid & 127;
        if (e < KK) sid[sub][e] = nidx[unit * KK + e];
        __syncthreads();
        float s = 0.f;
        #pragma unroll
        for (int k = 0; k < KK; k++)
            s += __ldg(&emb[sid[sub][k] * DD + e]);
        g_hbar[unit * DD + e] = s * (1.0f / (float)KK);
    } else {
        // ---- sum_alpha ----
        float th = theta_p[0];
        float s  = 0.f;
        for (int i = tid; i < EE; i += 256)
            s += expf(-th * (1.0f - tev[i]));
        #pragma unroll
        for (int o = 16; o; o >>= 1) s += __shfl_down_sync(0xffffffffu, s, o);
        int lane = tid & 31, w = tid >> 5;
        if (lane == 0) sw[w] = s;
        __syncthreads();
        if (tid == 0) {
            float tot = 0.f;
            #pragma unroll
            for (int i = 0; i < 8; i++) tot += sw[i];
            g_alpha = tot;
        }
    }
}

// =======================================================================
// K_B: tri | egemm  (512 threads, role by blockIdx)
// =======================================================================
__global__ void k_B(const float* __restrict__ Wb,
                    const float* __restrict__ bb) {
    __shared__ __align__(16) float sbuf[512 * 20];  // egemm 40 KB (reused for reduce)
    __shared__ __align__(16) unsigned sri[4][NW];   // tri rows
    __shared__ int sc[4][4];

    int b   = blockIdx.x;
    int tid = threadIdx.x;

    if (b < TRI_B) {
        // ---- triangles + clustering coeff, 4 rows per block ----
        int sub = tid >> 7;                // 0..3
        int t   = tid & 127;
        int i   = b * 4 + sub;
        sri[sub][t] = g_bits[i * NW + t];
        __syncthreads();
        unsigned w = sri[sub][t];
        const uint4* ri = (const uint4*)&sri[sub][0];
        int cnt = 0;
        while (w) {
            int bb2 = __ffs(w) - 1;
            w &= w - 1;
            int j = t * 32 + bb2;
            const uint4* rj = (const uint4*)&g_bits[j * NW];
            int s = 0;
            #pragma unroll 8
            for (int v = 0; v < 32; v++) {
                uint4 x = rj[v];
                uint4 y = ri[v];
                s += __popc(x.x & y.x) + __popc(x.y & y.y)
                   + __popc(x.z & y.z) + __popc(x.w & y.w);
            }
            cnt += s;
        }
        #pragma unroll
        for (int o = 16; o; o >>= 1) cnt += __shfl_down_sync(0xffffffffu, cnt, o);
        if ((t & 31) == 0) sc[sub][t >> 5] = cnt;
        __syncthreads();
        if (t == 0) {
            float tri = (float)(sc[sub][0] + sc[sub][1] + sc[sub][2] + sc[sub][3]);
            float d   = g_deg[i];
            float den = d * (d - 1.0f);
            if (den == 0.0f) den = 1e-6f;
            g_C[i] = 2.0f * tri / den;
        }
    } else {
        // ---- eps GEMM: eps = sigmoid((h_bar @ Wb + sum_r b)/4) ----
        int e  = tid & 127, g = tid >> 7;
        int n0 = (b - TRI_B) * 16;
        for (int idx = tid; idx < 16 * 512; idx += 512) {
            int rd = idx & 511, n = idx >> 9;
            sbuf[rd * 20 + n] = g_hbar[(n0 + n) * 512 + rd];
        }
        __syncthreads();
        unsigned long long acc[8];
        #pragma unroll
        for (int q = 0; q < 8; q++) acc[q] = 0ull;
        int rdbase = g * 128;
        #pragma unroll 2
        for (int i = 0; i < 128; i++) {
            int rd = rdbase + i;
            float wv = Wb[rd * DD + e];
            unsigned long long w2 = pk(wv, wv);
            const ulonglong2* row = (const ulonglong2*)&sbuf[rd * 20];
            #pragma unroll
            for (int q = 0; q < 4; q++) {
                ulonglong2 v = row[q];
                ffma2(acc[2 * q],     v.x, w2);
                ffma2(acc[2 * q + 1], v.y, w2);
            }
        }
        float a[16];
        #pragma unroll
        for (int q = 0; q < 8; q++) upk(a[2 * q], a[2 * q + 1], acc[q]);
        __syncthreads();
        if (g > 0) {
            #pragma unroll
            for (int n = 0; n < 16; n++)
                sbuf[((g - 1) * 16 + n) * DD + e] = a[n];
        }
        __syncthreads();
        if (g == 0) {
            float bsum = bb[e] + bb[DD + e] + bb[2 * DD + e] + bb[3 * DD + e];
            #pragma unroll
            for (int n = 0; n < 16; n++) {
                float t = a[n] + sbuf[n * DD + e]
                               + sbuf[(16 + n) * DD + e]
                               + sbuf[(32 + n) * DD + e];
                float h = (t + bsum) * 0.25f;
                g_eps[(n0 + n) * DD + e] = 1.0f / (1.0f + expf(-h));
            }
        }
    }
}

// =======================================================================
// K_C: per-pair score (warp per pair)
// =======================================================================
__global__ void k_pairs(const int*   __restrict__ pairs,
                        const float* __restrict__ emb,
                        const float* __restrict__ q1p,
                        const float* __restrict__ q2p,
                        float*       __restrict__ out) {
    int gw   = (blockIdx.x * blockDim.x + threadIdx.x) >> 5;
    int lane = threadIdx.x & 31;
    if (gw >= PP) return;
    int pm = pairs[gw * 2 + 0];
    int pn = pairs[gw * 2 + 1];

    float4 a  = ((const float4*)&g_proj[pm * DD])[lane];
    float4 b  = ((const float4*)&g_proj[pn * DD])[lane];
    float dx0 = a.x - b.x, dx1 = a.y - b.y, dx2 = a.z - b.z, dx3 = a.w - b.w;
    float s1  = dx0*dx0 + dx1*dx1 + dx2*dx2 + dx3*dx3;

    float4 ea = ((const float4*)&emb[pm * DD])[lane];
    float4 eb = ((const float4*)&emb[pn * DD])[lane];
    float e0 = ea.x - eb.x, e1 = ea.y - eb.y, e2 = ea.z - eb.z, e3 = ea.w - eb.w;
    float s2 = e0*e0 + e1*e1 + e2*e2 + e3*e3;

    float4 pa = ((const float4*)&g_eps[pm * DD])[lane];
    float4 pb = ((const float4*)&g_eps[pn * DD])[lane];
    float s3  = pa.x*pb.x + pa.y*pb.y + pa.z*pb.z + pa.w*pb.w;

    uint4 bm = ((const uint4*)&g_bits[pm * NW])[lane];
    uint4 bn = ((const uint4*)&g_bits[pn * NW])[lane];
    float cs = 0.f;
    {
        unsigned ws[4] = { bm.x & bn.x, bm.y & bn.y, bm.z & bn.z, bm.w & bn.w };
        #pragma unroll
        for (int c = 0; c < 4; c++) {
            unsigned w = ws[c];
            int j0 = (lane * 4 + c) * 32;
            while (w) {
                int bpos = __ffs(w) - 1;
                w &= w - 1;
                cs += g_C[j0 + bpos];
            }
        }
    }

    #pragma unroll
    for (int o = 16; o; o >>= 1) {
        s1 += __shfl_xor_sync(0xffffffffu, s1, o);
        s2 += __shfl_xor_sync(0xffffffffu, s2, o);
        s3 += __shfl_xor_sync(0xffffffffu, s3, o);
        cs += __shfl_xor_sync(0xffffffffu, cs, o);
    }

    if (lane == 0) {
        float gamma = -sqrtf(s1);
        float g     = -s2;
        float lamb  = gamma + g_alpha + cs * g + s3 * (1.0f / (float)DD);
        float lam   = expf(lamb);
        float z     = q1p[0] * lam + q2p[0];
        out[gw] = 1.0f / (1.0f + expf(-z));
    }
}

// ---------------- launcher ----------------
extern "C" void kernel_launch(void* const* d_in, const int* in_sizes, int n_in,
                              void* d_out, int out_size) {
    const int*   pairs   = (const int*)  d_in[0];
    const int*   adj     = (const int*)  d_in[1];
    const int*   nidx    = (const int*)  d_in[2];
    const int*   ntype   = (const int*)  d_in[3];
    const float* tev     = (const float*)d_in[4];
    const float* emb     = (const float*)d_in[5];
    const float* Wp      = (const float*)d_in[6];
    const float* Wb      = (const float*)d_in[7];
    const float* bb      = (const float*)d_in[8];
    const float* theta_p = (const float*)d_in[9];
    const float* q1p     = (const float*)d_in[10];
    const float* q2p     = (const float*)d_in[11];
    float*       out     = (float*)d_out;

    k_A    <<<GRID_A, 256>>>(adj, emb, Wp, ntype, nidx, tev, theta_p);
    k_B    <<<TRI_B + EG_B, 512>>>(Wb, bb);
    k_pairs<<<PP / 8, 256>>>(pairs, emb, q1p, q2p, out);
}

// round 5
// speedup vs baseline: 1.4875x; 1.3388x over previous
#include <cuda_runtime.h>
#include <cuda_bf16.h>
#include <cstdint>

// Problem constants
#define NN   4096
#define PP   32768
#define EE   4096
#define DD   128
#define RR   4
#define KK   16
#define NW   128       // 4096 bits / 32 words per adjacency row

// ---- K_A striping: group of 25 = 8 pack + 16 gather + 1 proj ----
#define GRID_A  (512 * 25 + 1)        // 12801 (+1 alpha block)
// ---- K_B striping: group of 9 = 8 tri + 1 egemm ----
#define GRID_B  (512 * 9)             // 4608

// ---------------- device scratch ----------------
__device__ unsigned g_bits[NN * NW];
__device__ float    g_C   [NN];
__device__ float    g_proj[NN * DD];
__device__ float    g_eps [NN * DD];
__device__ float    g_hbar[NN * RR * DD];   // [n][r*128+d]
__device__ float    g_alpha;

// ---------------- packed fp32x2 helpers (sm_100+) ----------------
__device__ __forceinline__ unsigned long long pk(float x, float y) {
    unsigned long long r;
    asm("mov.b64 %0, {%1, %2};" : "=l"(r) : "f"(x), "f"(y));
    return r;
}
__device__ __forceinline__ void upk(float& x, float& y, unsigned long long v) {
    asm("mov.b64 {%0, %1}, %2;" : "=f"(x), "=f"(y) : "l"(v));
}
__device__ __forceinline__ void ffma2(unsigned long long& d,
                                      unsigned long long a,
                                      unsigned long long b) {
    asm("fma.rn.f32x2 %0, %1, %2, %0;" : "+l"(d) : "l"(a), "l"(b));
}

// =======================================================================
// K_A: pack | gather | proj | alpha, striped for cross-role wave overlap
// =======================================================================
__global__ void __launch_bounds__(256, 5)
k_A(const int*   __restrict__ adj,
    const float* __restrict__ emb,
    const float* __restrict__ Wp,
    const int*   __restrict__ ntype,
    const int*   __restrict__ nidx,
    const float* __restrict__ tev,
    const float* __restrict__ theta_p) {
    __shared__ __align__(16) float semb[DD * 12];   // proj [d][n] pad 12
    __shared__ float sred[8 * DD];                  // proj partials
    __shared__ int   sty[8];
    __shared__ int   sid[2][KK];                    // gather ids
    __shared__ float sw[8];                         // alpha

    int b   = blockIdx.x;
    int tid = threadIdx.x;
    int lane = tid & 31, w = tid >> 5;

    if (b < 512 * 25) {
        int r = b % 25, q = b / 25;
        if (r < 8) {
            // ---- bitpack one adjacency row (8 warps, warp w -> words [w*16, w*16+16)) ----
            int row = q * 8 + r;
            const int* a = adj + (size_t)row * NN;
            int v[16];
            #pragma unroll
            for (int i = 0; i < 16; i++)
                v[i] = a[(w * 16 + i) * 32 + lane];      // MLP-16 front batch
            unsigned keep = 0;
            #pragma unroll
            for (int i = 0; i < 16; i++) {
                unsigned m = __ballot_sync(0xffffffffu, v[i] != 0);
                if (lane == i) keep = m;
            }
            if (lane < 16)
                g_bits[row * NW + w * 16 + lane] = keep; // coalesced 64B store
        } else if (r < 24) {
            // ---- neighbor gather -> h_bar, 2 (node,r) units per block ----
            int gb   = q * 16 + (r - 8);
            int sub  = tid >> 7;
            int unit = gb * 2 + sub;
            int e    = tid & 127;
            if (e < KK) sid[sub][e] = nidx[unit * KK + e];
            __syncthreads();
            float s = 0.f;
            #pragma unroll
            for (int k = 0; k < KK; k++)
                s += __ldg(&emb[sid[sub][k] * DD + e]);
            g_hbar[unit * DD + e] = s * (1.0f / (float)KK);
        } else {
            // ---- type-selected projection, 8-node tile ----
            int n0 = q * 8;
            int e  = tid & 127, g = tid >> 7;
            for (int idx = tid; idx < 8 * DD; idx += 256) {
                int d = idx & 127, n = idx >> 7;
                semb[d * 12 + n] = emb[(n0 + n) * DD + d];
            }
            if (tid < 8) sty[tid] = ntype[n0 + tid];
            __syncthreads();
            int ty[8];
            #pragma unroll
            for (int n = 0; n < 8; n++) ty[n] = sty[n];
            float acc[8] = {0.f,0.f,0.f,0.f,0.f,0.f,0.f,0.f};
            int dbase = g * 64;
            #pragma unroll 4
            for (int i = 0; i < 64; i++) {
                int d = dbase + i;
                float w0 = Wp[(0 * DD + d) * DD + e];
                float w1 = Wp[(1 * DD + d) * DD + e];
                float w2 = Wp[(2 * DD + d) * DD + e];
                const float4* row4 = (const float4*)&semb[d * 12];
                #pragma unroll
                for (int p = 0; p < 2; p++) {
                    float4 v4 = row4[p];
                    { int n=4*p+0; float wv=(ty[n]==0)?w0:((ty[n]==1)?w1:w2); acc[n]+=v4.x*wv; }
                    { int n=4*p+1; float wv=(ty[n]==0)?w0:((ty[n]==1)?w1:w2); acc[n]+=v4.y*wv; }
                    { int n=4*p+2; float wv=(ty[n]==0)?w0:((ty[n]==1)?w1:w2); acc[n]+=v4.z*wv; }
                    { int n=4*p+3; float wv=(ty[n]==0)?w0:((ty[n]==1)?w1:w2); acc[n]+=v4.w*wv; }
                }
            }
            if (g == 1) {
                #pragma unroll
                for (int n = 0; n < 8; n++) sred[n * DD + e] = acc[n];
            }
            __syncthreads();
            if (g == 0) {
                #pragma unroll
                for (int n = 0; n < 8; n++)
                    g_proj[(n0 + n) * DD + e] = acc[n] + sred[n * DD + e];
            }
        }
    } else {
        // ---- sum_alpha ----
        float th = theta_p[0];
        float s  = 0.f;
        for (int i = tid; i < EE; i += 256)
            s += expf(-th * (1.0f - tev[i]));
        #pragma unroll
        for (int o = 16; o; o >>= 1) s += __shfl_down_sync(0xffffffffu, s, o);
        if (lane == 0) sw[w] = s;
        __syncthreads();
        if (tid == 0) {
            float tot = 0.f;
            #pragma unroll
            for (int i = 0; i < 8; i++) tot += sw[i];
            g_alpha = tot;
        }
    }
}

// =======================================================================
// K_B: tri | egemm, striped (256 threads)
// =======================================================================
__global__ void __launch_bounds__(256, 6)
k_B(const float* __restrict__ Wb,
    const float* __restrict__ bb) {
    __shared__ __align__(16) float    sbuf[4096];   // egemm 16 KB (h tile / reduce)
    __shared__ __align__(16) unsigned sri[NW];      // tri: row i bits
    __shared__ int  list[256];                      // tri: neighbor list
    __shared__ int  scnt;
    __shared__ int  swsum[8];

    int b    = blockIdx.x;
    int tid  = threadIdx.x;
    int lane = tid & 31, w = tid >> 5;
    int r    = b % 9, q = b / 9;

    if (r < 8) {
        // ---------- triangles + clustering coeff, one row per block ----------
        int i = q * 8 + r;
        if (tid == 0) scnt = 0;
        if (tid < NW) sri[tid] = g_bits[i * NW + tid];
        __syncthreads();
        // build compact neighbor list
        if (tid < NW) {
            unsigned word = sri[tid];
            while (word) {
                int bit = __ffs(word) - 1;
                word &= word - 1;
                int pos = atomicAdd(&scnt, 1);
                list[pos] = tid * 32 + bit;
            }
        }
        __syncthreads();
        int cnt = scnt;
        // warp-per-neighbor coalesced scans, per-lane accumulators
        uint4 ri = ((const uint4*)sri)[lane];
        int my = 0;
        int idx = w;
        for (; idx + 8 < cnt; idx += 16) {
            int j0 = list[idx], j1 = list[idx + 8];
            uint4 x0 = ((const uint4*)&g_bits[j0 * NW])[lane];
            uint4 x1 = ((const uint4*)&g_bits[j1 * NW])[lane];
            my += __popc(x0.x & ri.x) + __popc(x0.y & ri.y)
                + __popc(x0.z & ri.z) + __popc(x0.w & ri.w);
            my += __popc(x1.x & ri.x) + __popc(x1.y & ri.y)
                + __popc(x1.z & ri.z) + __popc(x1.w & ri.w);
        }
        if (idx < cnt) {
            int j0 = list[idx];
            uint4 x0 = ((const uint4*)&g_bits[j0 * NW])[lane];
            my += __popc(x0.x & ri.x) + __popc(x0.y & ri.y)
                + __popc(x0.z & ri.z) + __popc(x0.w & ri.w);
        }
        #pragma unroll
        for (int o = 16; o; o >>= 1) my += __shfl_down_sync(0xffffffffu, my, o);
        if (lane == 0) swsum[w] = my;
        __syncthreads();
        if (tid == 0) {
            int tot = 0;
            #pragma unroll
            for (int k = 0; k < 8; k++) tot += swsum[k];
            float d   = (float)cnt;
            float den = d * (d - 1.0f);
            if (den == 0.0f) den = 1e-6f;
            g_C[i] = 2.0f * (float)tot / den;
        }
    } else {
        // ---------- eps GEMM: eps = sigmoid((h_bar @ Wb + sum_r b)/4), 8-node tile ----------
        int e = tid & 127, g = tid >> 7;
        int n0 = q * 8;
        for (int idx = tid; idx < 8 * 512; idx += 256) {
            int n = idx >> 9, rd = idx & 511;
            sbuf[rd * 8 + n] = g_hbar[(n0 + n) * 512 + rd];
        }
        __syncthreads();
        unsigned long long acc[4] = {0ull, 0ull, 0ull, 0ull};
        int rdbase = g * 256;
        #pragma unroll 2
        for (int i2 = 0; i2 < 256; i2++) {
            int rd = rdbase + i2;
            float wv = Wb[rd * DD + e];
            unsigned long long w2 = pk(wv, wv);
            const ulonglong2* row = (const ulonglong2*)&sbuf[rd * 8];
            ulonglong2 v0 = row[0];
            ulonglong2 v1 = row[1];
            ffma2(acc[0], v0.x, w2);
            ffma2(acc[1], v0.y, w2);
            ffma2(acc[2], v1.x, w2);
            ffma2(acc[3], v1.y, w2);
        }
        float a[8];
        #pragma unroll
        for (int p = 0; p < 4; p++) upk(a[2 * p], a[2 * p + 1], acc[p]);
        __syncthreads();                 // done reading sbuf
        if (g == 1) {
            #pragma unroll
            for (int n = 0; n < 8; n++) sbuf[n * DD + e] = a[n];
        }
        __syncthreads();
        if (g == 0) {
            float bsum = bb[e] + bb[DD + e] + bb[2 * DD + e] + bb[3 * DD + e];
            #pragma unroll
            for (int n = 0; n < 8; n++) {
                float t = a[n] + sbuf[n * DD + e];
                float h = (t + bsum) * 0.25f;
                g_eps[(n0 + n) * DD + e] = 1.0f / (1.0f + expf(-h));
            }
        }
    }
}

// =======================================================================
// K_C: per-pair score (warp per pair)
// =======================================================================
__global__ void __launch_bounds__(256)
k_pairs(const int*   __restrict__ pairs,
        const float* __restrict__ emb,
        const float* __restrict__ q1p,
        const float* __restrict__ q2p,
        float*       __restrict__ out) {
    int gw   = (blockIdx.x * blockDim.x + threadIdx.x) >> 5;
    int lane = threadIdx.x & 31;
    if (gw >= PP) return;
    int pm = pairs[gw * 2 + 0];
    int pn = pairs[gw * 2 + 1];

    float4 a  = ((const float4*)&g_proj[pm * DD])[lane];
    float4 b  = ((const float4*)&g_proj[pn * DD])[lane];
    float dx0 = a.x - b.x, dx1 = a.y - b.y, dx2 = a.z - b.z, dx3 = a.w - b.w;
    float s1  = dx0*dx0 + dx1*dx1 + dx2*dx2 + dx3*dx3;

    float4 ea = ((const float4*)&emb[pm * DD])[lane];
    float4 eb = ((const float4*)&emb[pn * DD])[lane];
    float e0 = ea.x - eb.x, e1 = ea.y - eb.y, e2 = ea.z - eb.z, e3 = ea.w - eb.w;
    float s2 = e0*e0 + e1*e1 + e2*e2 + e3*e3;

    float4 pa = ((const float4*)&g_eps[pm * DD])[lane];
    float4 pb = ((const float4*)&g_eps[pn * DD])[lane];
    float s3  = pa.x*pb.x + pa.y*pb.y + pa.z*pb.z + pa.w*pb.w;

    uint4 bm = ((const uint4*)&g_bits[pm * NW])[lane];
    uint4 bn = ((const uint4*)&g_bits[pn * NW])[lane];
    float cs = 0.f;
    {
        unsigned ws[4] = { bm.x & bn.x, bm.y & bn.y, bm.z & bn.z, bm.w & bn.w };
        #pragma unroll
        for (int c = 0; c < 4; c++) {
            unsigned word = ws[c];
            int j0 = (lane * 4 + c) * 32;
            while (word) {
                int bpos = __ffs(word) - 1;
                word &= word - 1;
                cs += g_C[j0 + bpos];
            }
        }
    }

    #pragma unroll
    for (int o = 16; o; o >>= 1) {
        s1 += __shfl_xor_sync(0xffffffffu, s1, o);
        s2 += __shfl_xor_sync(0xffffffffu, s2, o);
        s3 += __shfl_xor_sync(0xffffffffu, s3, o);
        cs += __shfl_xor_sync(0xffffffffu, cs, o);
    }

    if (lane == 0) {
        float gamma = -sqrtf(s1);
        float g     = -s2;
        float lamb  = gamma + g_alpha + cs * g + s3 * (1.0f / (float)DD);
        float lam   = expf(lamb);
        float z     = q1p[0] * lam + q2p[0];
        out[gw] = 1.0f / (1.0f + expf(-z));
    }
}

// ---------------- launcher ----------------
extern "C" void kernel_launch(void* const* d_in, const int* in_sizes, int n_in,
                              void* d_out, int out_size) {
    const int*   pairs   = (const int*)  d_in[0];
    const int*   adj     = (const int*)  d_in[1];
    const int*   nidx    = (const int*)  d_in[2];
    const int*   ntype   = (const int*)  d_in[3];
    const float* tev     = (const float*)d_in[4];
    const float* emb     = (const float*)d_in[5];
    const float* Wp      = (const float*)d_in[6];
    const float* Wb      = (const float*)d_in[7];
    const float* bb      = (const float*)d_in[8];
    const float* theta_p = (const float*)d_in[9];
    const float* q1p     = (const float*)d_in[10];
    const float* q2p     = (const float*)d_in[11];
    float*       out     = (float*)d_out;

    k_A    <<<GRID_A, 256>>>(adj, emb, Wp, ntype, nidx, tev, theta_p);
    k_B    <<<GRID_B, 256>>>(Wb, bb);
    k_pairs<<<PP / 8, 256>>>(pairs, emb, q1p, q2p, out);
}

// round 7
// speedup vs baseline: 1.5403x; 1.0355x over previous
#include <cuda_runtime.h>
#include <cuda_bf16.h>
#include <cstdint>

// Problem constants
#define NN   4096
#define PP   32768
#define EE   4096
#define DD   128
#define RR   4
#define KK   16
#define NW   128       // 4096 bits / 32 words per adjacency row

// ---- K_A striping: group of 13 = 8 pack + 4 gather + 1 proj (+1 alpha/zero) ----
#define GRID_A  (512 * 13 + 1)
// ---- K_B striping: group of 9 = 8 tri + 1 egemm ----
#define GRID_B  (512 * 9)

// ---------------- device scratch ----------------
__device__ unsigned g_bits  [NN * NW];
__device__ int      g_trid  [NN];           // triangle counts (atomic)
__device__ float    g_invden[NN];           // 2 / (deg*(deg-1) or 1e-6)
__device__ float    g_proj  [NN * DD];
__device__ float    g_eps   [NN * DD];
__device__ float    g_hbar  [NN * RR * DD]; // [n][r*128+d]
__device__ float    g_alpha;

// ---------------- packed fp32x2 helpers (sm_100+) ----------------
__device__ __forceinline__ unsigned long long pk(float x, float y) {
    unsigned long long r;
    asm("mov.b64 %0, {%1, %2};" : "=l"(r) : "f"(x), "f"(y));
    return r;
}
__device__ __forceinline__ void upk(float& x, float& y, unsigned long long v) {
    asm("mov.b64 {%0, %1}, %2;" : "=f"(x), "=f"(y) : "l"(v));
}
__device__ __forceinline__ void ffma2(unsigned long long& d,
                                      unsigned long long a,
                                      unsigned long long b) {
    asm("fma.rn.f32x2 %0, %1, %2, %0;" : "+l"(d) : "l"(a), "l"(b));
}

// =======================================================================
// K_A: pack | gather | proj | alpha+zero, striped
// =======================================================================
__global__ void __launch_bounds__(256)
k_A(const int*   __restrict__ adj,
    const float* __restrict__ emb,
    const float* __restrict__ Wp,
    const int*   __restrict__ ntype,
    const int*   __restrict__ nidx,
    const float* __restrict__ tev,
    const float* __restrict__ theta_p) {
    __shared__ __align__(16) float semb[DD * 12];   // proj [d][n] pad 12
    __shared__ float sred[8 * DD];                  // proj partials
    __shared__ int   sty[8];
    __shared__ int   sdeg[8];                       // pack
    __shared__ float sw[8];                         // alpha

    int b    = blockIdx.x;
    int tid  = threadIdx.x;
    int lane = tid & 31, w = tid >> 5;

    if (b < 512 * 13) {
        int r = b % 13, q = b / 13;
        if (r < 8) {
            // ---- bitpack one adjacency row + inv-denominator ----
            int row = q * 8 + r;
            const int* a = adj + (size_t)row * NN;
            int v[16];
            #pragma unroll
            for (int i = 0; i < 16; i++)
                v[i] = a[(w * 16 + i) * 32 + lane];      // MLP-16 front batch
            unsigned keep = 0;
            #pragma unroll
            for (int i = 0; i < 16; i++) {
                unsigned m = __ballot_sync(0xffffffffu, v[i] != 0);
                if (lane == i) keep = m;
            }
            if (lane < 16)
                g_bits[row * NW + w * 16 + lane] = keep; // coalesced 64B store
            int dsum = (lane < 16) ? __popc(keep) : 0;
            #pragma unroll
            for (int o = 16; o; o >>= 1)
                dsum += __shfl_down_sync(0xffffffffu, dsum, o);
            if (lane == 0) sdeg[w] = dsum;
            __syncthreads();
            if (tid == 0) {
                int s = 0;
                #pragma unroll
                for (int i = 0; i < 8; i++) s += sdeg[i];
                float d   = (float)s;
                float den = d * (d - 1.0f);
                if (den == 0.0f) den = 1e-6f;
                g_invden[row] = 2.0f / den;
            }
        } else if (r < 12) {
            // ---- neighbor gather: warp per (node,r) unit, float4 loads ----
            int gb   = q * 4 + (r - 8);          // 0..2047
            int unit = gb * 8 + w;               // 8 units per block
            const float4* e4 = (const float4*)emb;
            int nid = 0;
            if (lane < KK) nid = nidx[unit * KK + lane];
            float4 acc = make_float4(0.f, 0.f, 0.f, 0.f);
            #pragma unroll
            for (int k = 0; k < KK; k++) {
                int id = __shfl_sync(0xffffffffu, nid, k);
                float4 v = __ldg(&e4[id * 32 + lane]);
                acc.x += v.x; acc.y += v.y; acc.z += v.z; acc.w += v.w;
            }
            ((float4*)g_hbar)[unit * 32 + lane] =
                make_float4(acc.x * 0.0625f, acc.y * 0.0625f,
                            acc.z * 0.0625f, acc.w * 0.0625f);
        } else {
            // ---- type-selected projection, 8-node tile ----
            int n0 = q * 8;
            int e  = tid & 127, g = tid >> 7;
            for (int idx = tid; idx < 8 * DD; idx += 256) {
                int d = idx & 127, n = idx >> 7;
                semb[d * 12 + n] = emb[(n0 + n) * DD + d];
            }
            if (tid < 8) sty[tid] = ntype[n0 + tid];
            __syncthreads();
            int ty[8];
            #pragma unroll
            for (int n = 0; n < 8; n++) ty[n] = sty[n];
            float acc[8] = {0.f,0.f,0.f,0.f,0.f,0.f,0.f,0.f};
            int dbase = g * 64;
            #pragma unroll 4
            for (int i = 0; i < 64; i++) {
                int d = dbase + i;
                float w0 = Wp[(0 * DD + d) * DD + e];
                float w1 = Wp[(1 * DD + d) * DD + e];
                float w2 = Wp[(2 * DD + d) * DD + e];
                const float4* row4 = (const float4*)&semb[d * 12];
                #pragma unroll
                for (int p = 0; p < 2; p++) {
                    float4 v4 = row4[p];
                    { int n=4*p+0; float wv=(ty[n]==0)?w0:((ty[n]==1)?w1:w2); acc[n]+=v4.x*wv; }
                    { int n=4*p+1; float wv=(ty[n]==0)?w0:((ty[n]==1)?w1:w2); acc[n]+=v4.y*wv; }
                    { int n=4*p+2; float wv=(ty[n]==0)?w0:((ty[n]==1)?w1:w2); acc[n]+=v4.z*wv; }
                    { int n=4*p+3; float wv=(ty[n]==0)?w0:((ty[n]==1)?w1:w2); acc[n]+=v4.w*wv; }
                }
            }
            if (g == 1) {
                #pragma unroll
                for (int n = 0; n < 8; n++) sred[n * DD + e] = acc[n];
            }
            __syncthreads();
            if (g == 0) {
                #pragma unroll
                for (int n = 0; n < 8; n++)
                    g_proj[(n0 + n) * DD + e] = acc[n] + sred[n * DD + e];
            }
        }
    } else {
        // ---- zero g_trid (for K_B atomics) + sum_alpha ----
        #pragma unroll
        for (int i = 0; i < NN / 256; i++)
            g_trid[i * 256 + tid] = 0;
        float th = theta_p[0];
        float s  = 0.f;
        for (int i = tid; i < EE; i += 256)
            s += expf(-th * (1.0f - tev[i]));
        #pragma unroll
        for (int o = 16; o; o >>= 1) s += __shfl_down_sync(0xffffffffu, s, o);
        if (lane == 0) sw[w] = s;
        __syncthreads();
        if (tid == 0) {
            float tot = 0.f;
            #pragma unroll
            for (int i = 0; i < 8; i++) tot += sw[i];
            g_alpha = tot;
        }
    }
}

// =======================================================================
// K_B: tri (half-edge, symmetric atomics) | egemm, striped
// =======================================================================
__global__ void __launch_bounds__(256)
k_B(const float* __restrict__ Wb,
    const float* __restrict__ bb) {
    __shared__ __align__(16) float    sbuf[4096];   // egemm 16 KB
    __shared__ __align__(16) unsigned sri[NW];      // tri: row i bits
    __shared__ int  list[256];
    __shared__ int  scnt;
    __shared__ int  swsum[8];

    int b    = blockIdx.x;
    int tid  = threadIdx.x;
    int lane = tid & 31, w = tid >> 5;
    int r    = b % 9, q = b / 9;

    if (r < 8) {
        // ---------- half-edge triangle scan, one row per block ----------
        int i = q * 8 + r;
        if (tid == 0) scnt = 0;
        if (tid < NW) sri[tid] = g_bits[i * NW + tid];
        __syncthreads();
        // neighbors j < i only
        if (tid < NW) {
            unsigned word = sri[tid];
            int iw = i >> 5;
            if (tid == iw)      word &= (1u << (i & 31)) - 1u;
            else if (tid > iw)  word = 0u;
            while (word) {
                int bit = __ffs(word) - 1;
                word &= word - 1;
                int pos = atomicAdd(&scnt, 1);
                list[pos] = tid * 32 + bit;
            }
        }
        __syncthreads();
        int cnt = scnt;
        uint4 ri = ((const uint4*)sri)[lane];
        int my = 0;                                  // contribution to tri[i]
        for (int idx = w; idx < cnt; idx += 8) {
            int j = list[idx];
            uint4 x = ((const uint4*)&g_bits[j * NW])[lane];
            int s = __popc(x.x & ri.x) + __popc(x.y & ri.y)
                  + __popc(x.z & ri.z) + __popc(x.w & ri.w);
            #pragma unroll
            for (int o = 16; o; o >>= 1)
                s += __shfl_down_sync(0xffffffffu, s, o);
            if (lane == 0) {
                atomicAdd(&g_trid[j], s);            // symmetric half
                my += s;
            }
        }
        if (lane == 0) swsum[w] = my;
        __syncthreads();
        if (tid == 0) {
            int tot = 0;
            #pragma unroll
            for (int k = 0; k < 8; k++) tot += swsum[k];
            if (tot) atomicAdd(&g_trid[i], tot);
        }
    } else {
        // ---------- eps GEMM: eps = sigmoid((h_bar @ Wb + sum_r b)/4) ----------
        int e = tid & 127, g = tid >> 7;
        int n0 = q * 8;
        for (int idx = tid; idx < 8 * 512; idx += 256) {
            int n = idx >> 9, rd = idx & 511;
            sbuf[rd * 8 + n] = g_hbar[(n0 + n) * 512 + rd];
        }
        __syncthreads();
        unsigned long long acc[4] = {0ull, 0ull, 0ull, 0ull};
        int rdbase = g * 256;
        #pragma unroll 2
        for (int i2 = 0; i2 < 256; i2++) {
            int rd = rdbase + i2;
            float wv = Wb[rd * DD + e];
            unsigned long long w2 = pk(wv, wv);
            const ulonglong2* row = (const ulonglong2*)&sbuf[rd * 8];
            ulonglong2 v0 = row[0];
            ulonglong2 v1 = row[1];
            ffma2(acc[0], v0.x, w2);
            ffma2(acc[1], v0.y, w2);
            ffma2(acc[2], v1.x, w2);
            ffma2(acc[3], v1.y, w2);
        }
        float a[8];
        #pragma unroll
        for (int p = 0; p < 4; p++) upk(a[2 * p], a[2 * p + 1], acc[p]);
        __syncthreads();
        if (g == 1) {
            #pragma unroll
            for (int n = 0; n < 8; n++) sbuf[n * DD + e] = a[n];
        }
        __syncthreads();
        if (g == 0) {
            float bsum = bb[e] + bb[DD + e] + bb[2 * DD + e] + bb[3 * DD + e];
            #pragma unroll
            for (int n = 0; n < 8; n++) {
                float t = a[n] + sbuf[n * DD + e];
                float h = (t + bsum) * 0.25f;
                g_eps[(n0 + n) * DD + e] = 1.0f / (1.0f + expf(-h));
            }
        }
    }
}

// =======================================================================
// K_C: per-pair score (warp per pair), C computed inline from tri*invden
// =======================================================================
__global__ void __launch_bounds__(256)
k_pairs(const int*   __restrict__ pairs,
        const float* __restrict__ emb,
        const float* __restrict__ q1p,
        const float* __restrict__ q2p,
        float*       __restrict__ out) {
    int gw   = (blockIdx.x * blockDim.x + threadIdx.x) >> 5;
    int lane = threadIdx.x & 31;
    if (gw >= PP) return;
    int pm = pairs[gw * 2 + 0];
    int pn = pairs[gw * 2 + 1];

    float4 a  = ((const float4*)&g_proj[pm * DD])[lane];
    float4 b  = ((const float4*)&g_proj[pn * DD])[lane];
    float dx0 = a.x - b.x, dx1 = a.y - b.y, dx2 = a.z - b.z, dx3 = a.w - b.w;
    float s1  = dx0*dx0 + dx1*dx1 + dx2*dx2 + dx3*dx3;

    float4 ea = ((const float4*)&emb[pm * DD])[lane];
    float4 eb = ((const float4*)&emb[pn * DD])[lane];
    float e0 = ea.x - eb.x, e1 = ea.y - eb.y, e2 = ea.z - eb.z, e3 = ea.w - eb.w;
    float s2 = e0*e0 + e1*e1 + e2*e2 + e3*e3;

    float4 pa = ((const float4*)&g_eps[pm * DD])[lane];
    float4 pb = ((const float4*)&g_eps[pn * DD])[lane];
    float s3  = pa.x*pb.x + pa.y*pb.y + pa.z*pb.z + pa.w*pb.w;

    uint4 bm = ((const uint4*)&g_bits[pm * NW])[lane];
    uint4 bn = ((const uint4*)&g_bits[pn * NW])[lane];
    float cs = 0.f;
    {
        unsigned ws[4] = { bm.x & bn.x, bm.y & bn.y, bm.z & bn.z, bm.w & bn.w };
        #pragma unroll
        for (int c = 0; c < 4; c++) {
            unsigned word = ws[c];
            int j0 = (lane * 4 + c) * 32;
            while (word) {
                int bpos = __ffs(word) - 1;
                word &= word - 1;
                int j = j0 + bpos;
                cs += (float)g_trid[j] * g_invden[j];   // C[j] inline
            }
        }
    }

    #pragma unroll
    for (int o = 16; o; o >>= 1) {
        s1 += __shfl_xor_sync(0xffffffffu, s1, o);
        s2 += __shfl_xor_sync(0xffffffffu, s2, o);
        s3 += __shfl_xor_sync(0xffffffffu, s3, o);
        cs += __shfl_xor_sync(0xffffffffu, cs, o);
    }

    if (lane == 0) {
        float gamma = -sqrtf(s1);
        float g     = -s2;
        float lamb  = gamma + g_alpha + cs * g + s3 * (1.0f / (float)DD);
        float lam   = expf(lamb);
        float z     = q1p[0] * lam + q2p[0];
        out[gw] = 1.0f / (1.0f + expf(-z));
    }
}

// ---------------- launcher ----------------
extern "C" void kernel_launch(void* const* d_in, const int* in_sizes, int n_in,
                              void* d_out, int out_size) {
    const int*   pairs   = (const int*)  d_in[0];
    const int*   adj     = (const int*)  d_in[1];
    const int*   nidx    = (const int*)  d_in[2];
    const int*   ntype   = (const int*)  d_in[3];
    const float* tev     = (const float*)d_in[4];
    const float* emb     = (const float*)d_in[5];
    const float* Wp      = (const float*)d_in[6];
    const float* Wb      = (const float*)d_in[7];
    const float* bb      = (const float*)d_in[8];
    const float* theta_p = (const float*)d_in[9];
    const float* q1p     = (const float*)d_in[10];
    const float* q2p     = (const float*)d_in[11];
    float*       out     = (float*)d_out;

    k_A    <<<GRID_A, 256>>>(adj, emb, Wp, ntype, nidx, tev, theta_p);
    k_B    <<<GRID_B, 256>>>(Wb, bb);
    k_pairs<<<PP / 8, 256>>>(pairs, emb, q1p, q2p, out);
}